// round 14
// baseline (speedup 1.0000x reference)
#include <cuda_runtime.h>
#include <cuda_fp16.h>
#include <cstdint>
#include <math.h>

// ===================== problem constants =====================
#define D 128
#define NROWS (64 * 4096)          // B*T = 262144
#define NTILES (NROWS / 128)       // 2048
#define GRID_MAIN 148
#define NTHREADS 1024              // 32 warps = 8 groups x 4 warps; group: 16 rows, warp: 32 cols

// ===================== helpers =====================
__device__ __forceinline__ uint32_t smem_u32(const void* p) {
    uint32_t a;
    asm("{ .reg .u64 t; cvta.to.shared.u64 t, %1; cvt.u32.u64 %0, t; }" : "=r"(a) : "l"(p));
    return a;
}
__device__ __forceinline__ uint32_t packh2(float a, float b) {
    __half2 h = __floats2half2_rn(a, b);
    return *(uint32_t*)&h;
}
__device__ __forceinline__ uint32_t pack2h(__half a, __half b) {
    return (uint32_t)__half_as_ushort(a) | ((uint32_t)__half_as_ushort(b) << 16);
}
// fp16 two-term split (precompute only)
__device__ __forceinline__ void split2h(float x0, float x1, uint32_t& hi, uint32_t& lo) {
    __half h0 = __float2half_rn(x0), h1 = __float2half_rn(x1);
    hi = pack2h(h0, h1);
    lo = pack2h(__float2half_rn(x0 - __half2float(h0)),
                __float2half_rn(x1 - __half2float(h1)));
}
// tanh-form GELU via sigmoid: 0.5v(1+tanh(u)) = v * sigma(2u); max |diff vs exact| ~1e-4
__device__ __forceinline__ float gelu_fast(float v) {
    return v / (1.0f + __expf(-1.5957691216057308f * v * (1.0f + 0.044715f * v * v)));
}

#define MMA(c0, c1, c2, c3, a0, a1, a2, a3, b0, b1)                                   \
    asm volatile("mma.sync.aligned.m16n8k16.row.col.f32.f16.f16.f32 "                 \
                 "{%0,%1,%2,%3}, {%4,%5,%6,%7}, {%8,%9}, {%0,%1,%2,%3};"              \
                 : "+f"(c0), "+f"(c1), "+f"(c2), "+f"(c3)                             \
                 : "r"(a0), "r"(a1), "r"(a2), "r"(a3), "r"(b0), "r"(b1))

#define LDSM4(r0, r1, r2, r3, addr)                                                    \
    asm volatile("ldmatrix.sync.aligned.m8n8.x4.shared.b16 {%0,%1,%2,%3}, [%4];"       \
                 : "=r"(r0), "=r"(r1), "=r"(r2), "=r"(r3) : "r"(addr))

// named barrier for a 128-thread group (ids 1..8)
#define BARG(id) asm volatile("bar.sync %0, 128;" :: "r"(id) : "memory")

// ===================== SMEM map =====================
// Weight images: [n][k] fp16, 256B rows, XOR-swizzled 16B chunks
#define SW1  0          // W1 image (32 KB); Wb during precompute
#define SW2  32768      // W_out image (32 KB); T1 during precompute
#define SX   65536      // x image: 128 rows x 256B fp16 (32 KB)
#define SH   98304      // h image (32 KB)
#define SB1  131072
#define SB2  131584
#define SGAM 132096     // gamma (bg during precompute)
#define SBET 132608
#define SRED 133120     // 4 KB: LN group partials / bg scratch
#define SMEM_BYTES 137216

// Precompute k-step (2-term A hi/lo, single fp16 B): 16 rows x 32 cols, c[4][4].
__device__ __forceinline__ void pre_kstep(float (&c)[4][4],
                                          const uint32_t* aH, const uint32_t* aL,
                                          uint32_t base, uint32_t sAdd) {
#pragma unroll
    for (int j = 0; j < 2; j++) {
        uint32_t b0, b1, b2, b3;
        LDSM4(b0, b1, b2, b3, base + j * 4096 + sAdd);
        MMA(c[2 * j][0], c[2 * j][1], c[2 * j][2], c[2 * j][3],
            aH[0], aH[1], aH[2], aH[3], b0, b1);
        MMA(c[2 * j + 1][0], c[2 * j + 1][1], c[2 * j + 1][2], c[2 * j + 1][3],
            aH[0], aH[1], aH[2], aH[3], b2, b3);
        MMA(c[2 * j][0], c[2 * j][1], c[2 * j][2], c[2 * j][3],
            aL[0], aL[1], aL[2], aL[3], b0, b1);
        MMA(c[2 * j + 1][0], c[2 * j + 1][1], c[2 * j + 1][2], c[2 * j + 1][3],
            aL[0], aL[1], aL[2], aL[3], b2, b3);
    }
}

// A fragments (16 rows x k16) from a global fp32 row pointer (precompute only)
__device__ __forceinline__ void load_a_frags(const float* arow, int s,
                                             uint32_t (&aH)[4], uint32_t (&aL)[4]) {
    float2 v00 = *(const float2*)(arow + 16 * s);
    float2 v10 = *(const float2*)(arow + 16 * s + 8 * D);
    float2 v01 = *(const float2*)(arow + 16 * s + 8);
    float2 v11 = *(const float2*)(arow + 16 * s + 8 * D + 8);
    split2h(v00.x, v00.y, aH[0], aL[0]);
    split2h(v10.x, v10.y, aH[1], aL[1]);
    split2h(v01.x, v01.y, aH[2], aL[2]);
    split2h(v11.x, v11.y, aH[3], aL[3]);
}

// Store one fp32 into a single-fp16 B-image ([n][k], XOR swizzle) at (k=m, n).
__device__ __forceinline__ void store_bimg(char* smem, uint32_t dst, int m, int n, float v) {
    uint32_t off = ((uint32_t)(n * 256 + m * 2)) ^ (((uint32_t)n & 7u) << 4);
    *(__half*)(smem + dst + off) = __float2half_rn(v);
}

// ===================== single fused kernel =====================
__global__ void __launch_bounds__(NTHREADS, 1)
lgn_main(const float* __restrict__ x, const float* __restrict__ graph,
         const float* __restrict__ W_msg, const float* __restrict__ b_msg,
         const float* __restrict__ W_upd, const float* __restrict__ b_upd,
         const float* __restrict__ Wout, const float* __restrict__ bout,
         const float* __restrict__ gamma, const float* __restrict__ beta,
         float* __restrict__ out) {
    extern __shared__ char smem[];
    const uint32_t sb = smem_u32(smem);
    const int tid = threadIdx.x;
    const int wid = tid >> 5;
    const int l = tid & 31;
    const int g = wid >> 2;        // group 0..7: rows [16g, 16g+16)
    const int nq = wid & 3;        // col quarter: cols [32nq, 32nq+32)
    const int quad = l >> 2;
    const int qid = l & 3;
    const int mA = g * 16 + quad;
    const int mB = mA + 8;
    const int barid = g + 1;

    // B-image ldmatrix lane constants
    const uint32_t nlane = ((l >> 4) & 1) * 8 + (l & 7);
    const uint32_t laneN = nlane * 256;
    const uint32_t xorv  = (nlane & 7) << 4;
    const uint32_t kl2   = ((l >> 3) & 1) * 16;
    const uint32_t bq    = (uint32_t)nq * 8192 + laneN;    // col-quarter + lane row

    // A-image ldmatrix lane constants (x and h images)
    const uint32_t arow  = (l & 7) + ((l >> 3) & 1) * 8;
    const uint32_t akadd = ((l >> 4) & 1) * 16;
    const uint32_t axor  = (l & 7) << 4;
    const uint32_t sxA = sb + SX + g * 4096 + arow * 256;
    const uint32_t shA = sb + SH + g * 4096 + arow * 256;
    char* hw = smem + SH + g * 4096;       // h write side (by row)

    // x staging writer role: 128 group threads cover 16 rows x 128 cols
    const int idxg = nq * 32 + l;          // 0..127 within group
    const int xr = idxg >> 3;              // row 0..15
    const int xc = (idxg & 7) * 4;         // base col (float4)
    char* xw = smem + SX + g * 4096 + xr * 256;
    const uint32_t xswz = ((uint32_t)xr & 7u) << 4;

    // =========================================================================
    // In-kernel precompute (2-term A for accuracy; one-time):
    //   T1 = graph @ W_upd[128:], W1 = W_upd[:128] + W_msg @ T1
    //   bg = b_msg @ graph,       b1 = b_upd + bg @ W_upd[128:]
    // =========================================================================

    // ---- P0: stage Wb = W_upd[128:] as B image into SW1; bg partial sums ----
    for (int idx = tid; idx < D * D; idx += NTHREADS) {
        int k = idx >> 7, nn = idx & 127;
        store_bimg(smem, SW1, k, nn, W_upd[(D + k) * D + nn]);
    }
    {
        int j = tid & 127, hh = tid >> 7;   // hh in 0..7
        float p = 0.f;
#pragma unroll 8
        for (int gg = hh * 16; gg < hh * 16 + 16; gg++)
            p += b_msg[gg] * graph[gg * D + j];
        ((float*)(smem + SRED))[tid] = p;
    }
    __syncthreads();
    if (tid < D) {
        const float* sr = (const float*)(smem + SRED);
        float bg = 0.f;
#pragma unroll
        for (int hh = 0; hh < 8; hh++) bg += sr[tid + 128 * hh];
        ((float*)(smem + SGAM))[tid] = bg;
    }

    // ---- P1: T1 = graph @ Wb ; write T1^T -> SW2 B-image ----
    {
        float c[4][4];
#pragma unroll
        for (int j = 0; j < 4; j++) { c[j][0] = c[j][1] = c[j][2] = c[j][3] = 0.f; }
        const float* ar = graph + (size_t)mA * D + qid * 2;
#pragma unroll
        for (int s = 0; s < 8; s++) {
            uint32_t aH[4], aL[4];
            load_a_frags(ar, s, aH, aL);
            pre_kstep(c, aH, aL, sb + SW1, bq + (((uint32_t)(32 * s) + kl2) ^ xorv));
        }
#pragma unroll
        for (int j = 0; j < 4; j++) {
            int n0 = nq * 32 + 8 * j + qid * 2;
            store_bimg(smem, SW2, mA, n0,     c[j][0]);
            store_bimg(smem, SW2, mA, n0 + 1, c[j][1]);
            store_bimg(smem, SW2, mB, n0,     c[j][2]);
            store_bimg(smem, SW2, mB, n0 + 1, c[j][3]);
        }
    }
    __syncthreads();

    // ---- P2: W1 = W_upd[:128] + W_msg @ T1 ; write -> SW1 B-image ----
    {
        float c[4][4];
#pragma unroll
        for (int j = 0; j < 4; j++) { c[j][0] = c[j][1] = c[j][2] = c[j][3] = 0.f; }
        const float* ar = W_msg + (size_t)mA * D + qid * 2;
#pragma unroll
        for (int s = 0; s < 8; s++) {
            uint32_t aH[4], aL[4];
            load_a_frags(ar, s, aH, aL);
            pre_kstep(c, aH, aL, sb + SW2, bq + (((uint32_t)(32 * s) + kl2) ^ xorv));
        }
#pragma unroll
        for (int j = 0; j < 4; j++) {   // += W_upd top half
            int n0 = nq * 32 + 8 * j + qid * 2;
            float2 tA = *(const float2*)(W_upd + (size_t)mA * D + n0);
            float2 tB = *(const float2*)(W_upd + (size_t)mB * D + n0);
            c[j][0] += tA.x; c[j][1] += tA.y; c[j][2] += tB.x; c[j][3] += tB.y;
        }
        // SW1 (Wb) dead after P1's sync -> safe to overwrite
#pragma unroll
        for (int j = 0; j < 4; j++) {
            int n0 = nq * 32 + 8 * j + qid * 2;
            store_bimg(smem, SW1, mA, n0,     c[j][0]);
            store_bimg(smem, SW1, mA, n0 + 1, c[j][1]);
            store_bimg(smem, SW1, mB, n0,     c[j][2]);
            store_bimg(smem, SW1, mB, n0 + 1, c[j][3]);
        }
    }
    __syncthreads();

    // ---- P3: stage W_out -> SW2 (T1 dead); b1 from bg; final vectors ----
    for (int idx = tid; idx < D * D; idx += NTHREADS) {
        int k = idx >> 7, nn = idx & 127;
        store_bimg(smem, SW2, k, nn, Wout[k * D + nn]);
    }
    if (tid < D) {
        const float* bgv = (const float*)(smem + SGAM);
        float acc = b_upd[tid];
#pragma unroll 8
        for (int h = 0; h < D; h++)
            acc += bgv[h] * W_upd[(D + h) * D + tid];
        ((float*)(smem + SB1))[tid] = acc;
    }
    __syncthreads();
    if (tid < D) {
        ((float*)(smem + SB2))[tid]  = bout[tid];
        ((float*)(smem + SGAM))[tid] = gamma[tid];
        ((float*)(smem + SBET))[tid] = beta[tid];
    }
    __syncthreads();

    const float* b1s = (const float*)(smem + SB1);
    const float* b2s = (const float*)(smem + SB2);
    const float* gms = (const float*)(smem + SGAM);
    const float* bts = (const float*)(smem + SBET);

    // =========================================================================
    // Main loop (single fp16): per 128-row tile: y = LN( gelu(x@W1+b1) @ W2 + b2 )
    // =========================================================================
    for (int t = blockIdx.x; t < NTILES; t += gridDim.x) {
        // ---- stage x (group rows) into fp16 A-image; coalesced LDG.128 ----
        {
            const float4* xp = (const float4*)(x + (size_t)t * (128 * D) +
                                               (size_t)(g * 16 + xr) * D + xc);
#pragma unroll
            for (int i = 0; i < 4; i++) {
                float4 v = xp[8 * i];
                uint32_t off = ((uint32_t)((xc + 32 * i) * 2)) ^ xswz;
                *(uint2*)(xw + off) = make_uint2(packh2(v.x, v.y), packh2(v.z, v.w));
            }
        }
        BARG(barid);   // x image ready (bar.sync drains STS)

        // ---- GEMM1: C1 = x @ W1 + b1  (warp's 32-col quarter) ----
        float c1[4][4];
#pragma unroll
        for (int j = 0; j < 4; j++) {
            float2 bb = *(const float2*)(b1s + nq * 32 + 8 * j + qid * 2);
            c1[j][0] = bb.x; c1[j][1] = bb.y; c1[j][2] = bb.x; c1[j][3] = bb.y;
        }
#pragma unroll
        for (int s = 0; s < 8; s++) {
            uint32_t a0, a1, a2, a3;
            LDSM4(a0, a1, a2, a3, sxA + (((uint32_t)(32 * s) + akadd) ^ axor));
            uint32_t sAdd = bq + (((uint32_t)(32 * s) + kl2) ^ xorv);
#pragma unroll
            for (int j = 0; j < 2; j++) {
                uint32_t b0, b1, b2, b3;
                LDSM4(b0, b1, b2, b3, sb + SW1 + j * 4096 + sAdd);
                MMA(c1[2 * j][0], c1[2 * j][1], c1[2 * j][2], c1[2 * j][3],
                    a0, a1, a2, a3, b0, b1);
                MMA(c1[2 * j + 1][0], c1[2 * j + 1][1], c1[2 * j + 1][2], c1[2 * j + 1][3],
                    a0, a1, a2, a3, b2, b3);
            }
        }

        // ---- epilogue 1: fast GELU, fp16 pack, stage h (warp's k-slice) ----
#pragma unroll
        for (int j = 0; j < 4; j++) {
            uint32_t kb = (uint32_t)(nq * 64 + 16 * j + 4 * qid);
            uint32_t hA = packh2(gelu_fast(c1[j][0]), gelu_fast(c1[j][1]));
            uint32_t hB = packh2(gelu_fast(c1[j][2]), gelu_fast(c1[j][3]));
            uint32_t sw = kb ^ ((uint32_t)quad << 4);
            *(uint32_t*)(hw + (uint32_t)quad * 256 + sw) = hA;
            *(uint32_t*)(hw + (uint32_t)(quad + 8) * 256 + sw) = hB;
        }
        BARG(barid);   // h image ready

        // ---- GEMM2: C2 = h @ W_out + b_out ----
        float c2[4][4];
#pragma unroll
        for (int j = 0; j < 4; j++) {
            float2 bb = *(const float2*)(b2s + nq * 32 + 8 * j + qid * 2);
            c2[j][0] = bb.x; c2[j][1] = bb.y; c2[j][2] = bb.x; c2[j][3] = bb.y;
        }
#pragma unroll
        for (int s = 0; s < 8; s++) {
            uint32_t a0, a1, a2, a3;
            LDSM4(a0, a1, a2, a3, shA + (((uint32_t)(32 * s) + akadd) ^ axor));
            uint32_t sAdd = bq + (((uint32_t)(32 * s) + kl2) ^ xorv);
#pragma unroll
            for (int j = 0; j < 2; j++) {
                uint32_t b0, b1, b2, b3;
                LDSM4(b0, b1, b2, b3, sb + SW2 + j * 4096 + sAdd);
                MMA(c2[2 * j][0], c2[2 * j][1], c2[2 * j][2], c2[2 * j][3],
                    a0, a1, a2, a3, b0, b1);
                MMA(c2[2 * j + 1][0], c2[2 * j + 1][1], c2[2 * j + 1][2], c2[2 * j + 1][3],
                    a0, a1, a2, a3, b2, b3);
            }
        }

        // ---- epilogue 2: LayerNorm (quad bfly + 4-warp exchange) + store ----
        float sA = 0.f, qA = 0.f, sB = 0.f, qB = 0.f;
#pragma unroll
        for (int j = 0; j < 4; j++) {
            sA += c2[j][0] + c2[j][1];
            qA += c2[j][0] * c2[j][0] + c2[j][1] * c2[j][1];
            sB += c2[j][2] + c2[j][3];
            qB += c2[j][2] * c2[j][2] + c2[j][3] * c2[j][3];
        }
#pragma unroll
        for (int m = 1; m < 4; m <<= 1) {
            sA += __shfl_xor_sync(0xFFFFFFFFu, sA, m);
            qA += __shfl_xor_sync(0xFFFFFFFFu, qA, m);
            sB += __shfl_xor_sync(0xFFFFFFFFu, sB, m);
            qB += __shfl_xor_sync(0xFFFFFFFFu, qB, m);
        }
        if (qid == 0) {
            *(float4*)(smem + SRED + ((g * 32 + nq * 8 + quad) << 4)) =
                make_float4(sA, qA, sB, qB);
        }
        BARG(barid);   // partials visible; also fences x/h reads before next tile
        sA = 0.f; qA = 0.f; sB = 0.f; qB = 0.f;
#pragma unroll
        for (int w = 0; w < 4; w++) {
            float4 o = *(const float4*)(smem + SRED + ((g * 32 + w * 8 + quad) << 4));
            sA += o.x; qA += o.y; sB += o.z; qB += o.w;
        }
        float mnA = sA * (1.0f / 128.0f);
        float iA = rsqrtf(qA * (1.0f / 128.0f) - mnA * mnA + 1e-5f);
        float mnB = sB * (1.0f / 128.0f);
        float iB = rsqrtf(qB * (1.0f / 128.0f) - mnB * mnB + 1e-5f);

        float* oA = out + (size_t)t * (128 * D) + (size_t)mA * D;
        float* oB = out + (size_t)t * (128 * D) + (size_t)mB * D;
#pragma unroll
        for (int j = 0; j < 4; j++) {
            int n0 = nq * 32 + 8 * j + qid * 2;
            float2 gm = *(const float2*)(gms + n0);
            float2 bt = *(const float2*)(bts + n0);
            float2 rA, rB;
            rA.x = (c2[j][0] - mnA) * iA * gm.x + bt.x;
            rA.y = (c2[j][1] - mnA) * iA * gm.y + bt.y;
            rB.x = (c2[j][2] - mnB) * iB * gm.x + bt.x;
            rB.y = (c2[j][3] - mnB) * iB * gm.y + bt.y;
            *(float2*)(oA + n0) = rA;
            *(float2*)(oB + n0) = rB;
        }
    }
}

// ===================== launch (single kernel per call) =====================
extern "C" void kernel_launch(void* const* d_in, const int* in_sizes, int n_in,
                              void* d_out, int out_size) {
    const float* x     = (const float*)d_in[0];
    const float* graph = (const float*)d_in[1];
    const float* W_msg = (const float*)d_in[2];
    const float* b_msg = (const float*)d_in[3];
    const float* W_upd = (const float*)d_in[4];
    const float* b_upd = (const float*)d_in[5];
    const float* W_out = (const float*)d_in[6];
    const float* b_out = (const float*)d_in[7];
    const float* gamma = (const float*)d_in[8];
    const float* beta  = (const float*)d_in[9];
    float* out = (float*)d_out;

    cudaFuncSetAttribute(lgn_main, cudaFuncAttributeMaxDynamicSharedMemorySize, SMEM_BYTES);

    lgn_main<<<GRID_MAIN, NTHREADS, SMEM_BYTES>>>(
        x, graph, W_msg, b_msg, W_upd, b_upd, W_out, b_out, gamma, beta, out);
}

// round 15
// speedup vs baseline: 1.3032x; 1.3032x over previous
#include <cuda_runtime.h>
#include <cuda_fp16.h>
#include <cstdint>
#include <math.h>

// ===================== problem constants =====================
#define D 128
#define NROWS (64 * 4096)          // B*T = 262144
#define NTILES (NROWS / 128)       // 2048
#define GRID_MAIN 148
#define NTHREADS 512               // 16 warps = 8 pairs; pair owns 16 rows, warp owns 64 cols

// ===================== helpers =====================
__device__ __forceinline__ uint32_t smem_u32(const void* p) {
    uint32_t a;
    asm("{ .reg .u64 t; cvta.to.shared.u64 t, %1; cvt.u32.u64 %0, t; }" : "=r"(a) : "l"(p));
    return a;
}
__device__ __forceinline__ uint32_t pack2h(__half a, __half b) {
    return (uint32_t)__half_as_ushort(a) | ((uint32_t)__half_as_ushort(b) << 16);
}
__device__ __forceinline__ uint32_t packh2(float a, float b) {
    __half2 h = __floats2half2_rn(a, b);
    return *(uint32_t*)&h;
}
// fp16 two-term split: x = hi + lo
__device__ __forceinline__ void split2h(float x0, float x1, uint32_t& hi, uint32_t& lo) {
    __half h0 = __float2half_rn(x0), h1 = __float2half_rn(x1);
    hi = pack2h(h0, h1);
    lo = pack2h(__float2half_rn(x0 - __half2float(h0)),
                __float2half_rn(x1 - __half2float(h1)));
}
// tanh-form GELU via sigmoid: 0.5v(1+tanh(u)) = v * sigma(2u); |diff vs exact| <= ~1e-4 rel scale
__device__ __forceinline__ float gelu_fast(float v) {
    return v / (1.0f + __expf(-1.5957691216057308f * v * (1.0f + 0.044715f * v * v)));
}

#define MMA(c0, c1, c2, c3, a0, a1, a2, a3, b0, b1)                                   \
    asm volatile("mma.sync.aligned.m16n8k16.row.col.f32.f16.f16.f32 "                 \
                 "{%0,%1,%2,%3}, {%4,%5,%6,%7}, {%8,%9}, {%0,%1,%2,%3};"              \
                 : "+f"(c0), "+f"(c1), "+f"(c2), "+f"(c3)                             \
                 : "r"(a0), "r"(a1), "r"(a2), "r"(a3), "r"(b0), "r"(b1))

#define LDSM4(r0, r1, r2, r3, addr)                                                    \
    asm volatile("ldmatrix.sync.aligned.m8n8.x4.shared.b16 {%0,%1,%2,%3}, [%4];"       \
                 : "=r"(r0), "=r"(r1), "=r"(r2), "=r"(r3) : "r"(addr))

// named barrier for a 64-thread pair (ids 1..8)
#define BARP(id) asm volatile("bar.sync %0, 64;" :: "r"(id) : "memory")

// ===================== SMEM map =====================
// Weight images: [n][k] fp16, 256B rows, XOR-swizzled 16B chunks (conflict-free ldmatrix)
#define SW1  0          // W1 image (32 KB); Wb during precompute
#define SW2  32768      // W_out image (32 KB); T1 during precompute
#define SHH  65536      // h staging: 8 pairs * 4 KB (16 rows x 256B, A layout) -- hi only
#define SB1  98304      // b1
#define SB2  98816      // b_out
#define SGAM 99328      // gamma (bg during precompute)
#define SBET 99840      // beta
#define SRED 100352     // 2 KB: LN pair partials / bg scratch
#define SMEM_BYTES 102400

// One k-step (K=16) of a 16x64 half-warp GEMM, 2-term fp16 (A split hi/lo, B single).
// Loads all 4 B-LDSM4 first, then issues 16 MMAs as one burst.
__device__ __forceinline__ void pair_kstep2(float (&c)[8][4],
                                            const uint32_t* aH, const uint32_t* aL,
                                            uint32_t base, uint32_t sAdd) {
    uint32_t b[4][4];
#pragma unroll
    for (int j = 0; j < 4; j++)
        LDSM4(b[j][0], b[j][1], b[j][2], b[j][3], base + j * 4096 + sAdd);
#pragma unroll
    for (int j = 0; j < 4; j++) {
        MMA(c[2 * j][0], c[2 * j][1], c[2 * j][2], c[2 * j][3],
            aH[0], aH[1], aH[2], aH[3], b[j][0], b[j][1]);
        MMA(c[2 * j + 1][0], c[2 * j + 1][1], c[2 * j + 1][2], c[2 * j + 1][3],
            aH[0], aH[1], aH[2], aH[3], b[j][2], b[j][3]);
    }
#pragma unroll
    for (int j = 0; j < 4; j++) {
        MMA(c[2 * j][0], c[2 * j][1], c[2 * j][2], c[2 * j][3],
            aL[0], aL[1], aL[2], aL[3], b[j][0], b[j][1]);
        MMA(c[2 * j + 1][0], c[2 * j + 1][1], c[2 * j + 1][2], c[2 * j + 1][3],
            aL[0], aL[1], aL[2], aL[3], b[j][2], b[j][3]);
    }
}

// 1-term variant (A hi only) for GEMM2: 4 B-LDSM4 then 8 MMAs.
__device__ __forceinline__ void pair_kstep1(float (&c)[8][4], const uint32_t* aH,
                                            uint32_t base, uint32_t sAdd) {
    uint32_t b[4][4];
#pragma unroll
    for (int j = 0; j < 4; j++)
        LDSM4(b[j][0], b[j][1], b[j][2], b[j][3], base + j * 4096 + sAdd);
#pragma unroll
    for (int j = 0; j < 4; j++) {
        MMA(c[2 * j][0], c[2 * j][1], c[2 * j][2], c[2 * j][3],
            aH[0], aH[1], aH[2], aH[3], b[j][0], b[j][1]);
        MMA(c[2 * j + 1][0], c[2 * j + 1][1], c[2 * j + 1][2], c[2 * j + 1][3],
            aH[0], aH[1], aH[2], aH[3], b[j][2], b[j][3]);
    }
}

// A fragments (16 rows x k16) straight from a global fp32 row pointer, fp16 hi/lo split
__device__ __forceinline__ void load_a_frags(const float* arow, int s,
                                             uint32_t (&aH)[4], uint32_t (&aL)[4]) {
    float2 v00 = *(const float2*)(arow + 16 * s);
    float2 v10 = *(const float2*)(arow + 16 * s + 8 * D);
    float2 v01 = *(const float2*)(arow + 16 * s + 8);
    float2 v11 = *(const float2*)(arow + 16 * s + 8 * D + 8);
    split2h(v00.x, v00.y, aH[0], aL[0]);
    split2h(v10.x, v10.y, aH[1], aL[1]);
    split2h(v01.x, v01.y, aH[2], aL[2]);
    split2h(v11.x, v11.y, aH[3], aL[3]);
}

// Store one fp32 value into a single-fp16 B-image ([n][k] layout, XOR swizzle) at (k=m, n).
__device__ __forceinline__ void store_bimg(char* smem, uint32_t dst, int m, int n, float v) {
    uint32_t off = ((uint32_t)(n * 256 + m * 2)) ^ (((uint32_t)n & 7u) << 4);
    *(__half*)(smem + dst + off) = __float2half_rn(v);
}

// ===================== single fused kernel =====================
__global__ void __launch_bounds__(NTHREADS, 1)
lgn_main(const float* __restrict__ x, const float* __restrict__ graph,
         const float* __restrict__ W_msg, const float* __restrict__ b_msg,
         const float* __restrict__ W_upd, const float* __restrict__ b_upd,
         const float* __restrict__ Wout, const float* __restrict__ bout,
         const float* __restrict__ gamma, const float* __restrict__ beta,
         float* __restrict__ out) {
    extern __shared__ char smem[];
    const uint32_t sb = smem_u32(smem);
    const int tid = threadIdx.x;
    const int wid = tid >> 5;
    const int l = tid & 31;
    const int pair = wid >> 1;     // 0..7: owns rows [16*pair, 16*pair+16)
    const int half = wid & 1;      // 0: cols 0-63, 1: cols 64-127
    const int quad = l >> 2;
    const int qid = l & 3;
    const int mA = pair * 16 + quad;
    const int mB = mA + 8;
    const int nh = half * 64;

    // B-image ldmatrix lane constants
    const uint32_t nlane = ((l >> 4) & 1) * 8 + (l & 7);
    const uint32_t laneN = nlane * 256;
    const uint32_t xorv  = (nlane & 7) << 4;
    const uint32_t kl2   = ((l >> 3) & 1) * 16;
    const uint32_t bhl   = (uint32_t)half * 16384 + laneN;   // half col offset + lane row

    // h-staging (A-image) lane constants
    const uint32_t arow  = (l & 7) + ((l >> 3) & 1) * 8;
    const uint32_t akadd = ((l >> 4) & 1) * 16;
    const uint32_t axor  = (l & 7) << 4;
    const uint32_t shpH  = sb + SHH + pair * 4096 + arow * 256;
    char* hwH = smem + SHH + pair * 4096;   // write side (by row)
    const int barid = pair + 1;

    // =========================================================================
    // In-kernel precompute (2-term A throughout for accuracy):
    //   T1 = graph @ W_upd[128:], W1 = W_upd[:128] + W_msg @ T1
    //   bg = b_msg @ graph,       b1 = b_upd + bg @ W_upd[128:]
    // =========================================================================

    // ---- P0: stage Wb = W_upd[128:] as B image into SW1; bg quarter sums ----
    for (int idx = tid; idx < D * D; idx += NTHREADS) {
        int k = idx >> 7, n = idx & 127;
        store_bimg(smem, SW1, k, n, W_upd[(D + k) * D + n]);
    }
    {
        int j = tid & 127, hh = tid >> 7;   // hh in 0..3
        float p = 0.f;
#pragma unroll 8
        for (int g = hh * 32; g < hh * 32 + 32; g++)
            p += b_msg[g] * graph[g * D + j];
        ((float*)(smem + SRED))[tid] = p;
    }
    __syncthreads();
    if (tid < D) {
        const float* sr = (const float*)(smem + SRED);
        ((float*)(smem + SGAM))[tid] = sr[tid] + sr[tid + 128] + sr[tid + 256] + sr[tid + 384];
    }

    // ---- P1: T1 = graph @ Wb ; write T1^T -> SW2 B-image ----
    {
        float c[8][4];
#pragma unroll
        for (int j = 0; j < 8; j++) { c[j][0] = c[j][1] = c[j][2] = c[j][3] = 0.f; }
        const float* ar = graph + (size_t)mA * D + qid * 2;
#pragma unroll
        for (int s = 0; s < 8; s++) {
            uint32_t aH[4], aL[4];
            load_a_frags(ar, s, aH, aL);
            pair_kstep2(c, aH, aL, sb + SW1, bhl + (((uint32_t)(32 * s) + kl2) ^ xorv));
        }
#pragma unroll
        for (int j = 0; j < 8; j++) {
            int n0 = nh + 8 * j + qid * 2;
            store_bimg(smem, SW2, mA, n0,     c[j][0]);
            store_bimg(smem, SW2, mA, n0 + 1, c[j][1]);
            store_bimg(smem, SW2, mB, n0,     c[j][2]);
            store_bimg(smem, SW2, mB, n0 + 1, c[j][3]);
        }
    }
    __syncthreads();

    // ---- P2: W1 = W_upd[:128] + W_msg @ T1 ; write -> SW1 B-image ----
    {
        float c[8][4];
#pragma unroll
        for (int j = 0; j < 8; j++) { c[j][0] = c[j][1] = c[j][2] = c[j][3] = 0.f; }
        const float* ar = W_msg + (size_t)mA * D + qid * 2;
#pragma unroll
        for (int s = 0; s < 8; s++) {
            uint32_t aH[4], aL[4];
            load_a_frags(ar, s, aH, aL);
            pair_kstep2(c, aH, aL, sb + SW2, bhl + (((uint32_t)(32 * s) + kl2) ^ xorv));
        }
#pragma unroll
        for (int j = 0; j < 8; j++) {   // += W_upd top half
            int n0 = nh + 8 * j + qid * 2;
            float2 tA = *(const float2*)(W_upd + (size_t)mA * D + n0);
            float2 tB = *(const float2*)(W_upd + (size_t)mB * D + n0);
            c[j][0] += tA.x; c[j][1] += tA.y; c[j][2] += tB.x; c[j][3] += tB.y;
        }
        // SW1 (Wb) dead after P1's sync -> safe to overwrite
#pragma unroll
        for (int j = 0; j < 8; j++) {
            int n0 = nh + 8 * j + qid * 2;
            store_bimg(smem, SW1, mA, n0,     c[j][0]);
            store_bimg(smem, SW1, mA, n0 + 1, c[j][1]);
            store_bimg(smem, SW1, mB, n0,     c[j][2]);
            store_bimg(smem, SW1, mB, n0 + 1, c[j][3]);
        }
    }
    __syncthreads();

    // ---- P3: stage W_out -> SW2 (T1 dead); b1 from bg; final vectors ----
    for (int idx = tid; idx < D * D; idx += NTHREADS) {
        int k = idx >> 7, n = idx & 127;
        store_bimg(smem, SW2, k, n, Wout[k * D + n]);
    }
    if (tid < D) {
        const float* bgv = (const float*)(smem + SGAM);
        float acc = b_upd[tid];
#pragma unroll 8
        for (int h = 0; h < D; h++)
            acc += bgv[h] * W_upd[(D + h) * D + tid];
        ((float*)(smem + SB1))[tid] = acc;
    }
    __syncthreads();
    if (tid < D) {
        ((float*)(smem + SB2))[tid]  = bout[tid];
        ((float*)(smem + SGAM))[tid] = gamma[tid];
        ((float*)(smem + SBET))[tid] = beta[tid];
    }
    __syncthreads();

    const float* b1s = (const float*)(smem + SB1);
    const float* b2s = (const float*)(smem + SB2);
    const float* gms = (const float*)(smem + SGAM);
    const float* bts = (const float*)(smem + SBET);

    // =========================================================================
    // Main loop: per 128-row tile:  y = LN( gelu(x@W1 + b1) @ W2 + b2 )
    // =========================================================================
    for (int t = blockIdx.x; t < NTILES; t += gridDim.x) {
        const float* xrow = x + (size_t)t * (128 * D) + (size_t)mA * D + qid * 2;

        // ---- GEMM1: C1 = x @ W1 + b1  (warp's 64-col half; 2-term x) ----
        float c1[8][4];
#pragma unroll
        for (int j = 0; j < 8; j++) {
            float2 bb = *(const float2*)(b1s + nh + 8 * j + qid * 2);
            c1[j][0] = bb.x; c1[j][1] = bb.y; c1[j][2] = bb.x; c1[j][3] = bb.y;
        }
#pragma unroll
        for (int s = 0; s < 8; s++) {
            uint32_t aH[4], aL[4];
            load_a_frags(xrow, s, aH, aL);
            pair_kstep2(c1, aH, aL, sb + SW1, bhl + (((uint32_t)(32 * s) + kl2) ^ xorv));
        }

        // ---- epilogue 1: fast GELU, single-fp16 pack, stage h (warp's k-half) ----
#pragma unroll
        for (int j = 0; j < 8; j++) {
            uint32_t kb = (uint32_t)(half * 128 + 16 * j + 4 * qid);
            uint32_t hA = packh2(gelu_fast(c1[j][0]), gelu_fast(c1[j][1]));
            uint32_t hB = packh2(gelu_fast(c1[j][2]), gelu_fast(c1[j][3]));
            uint32_t sw = kb ^ ((uint32_t)quad << 4);
            *(uint32_t*)(hwH + (uint32_t)quad * 256 + sw) = hA;
            *(uint32_t*)(hwH + (uint32_t)(quad + 8) * 256 + sw) = hB;
        }
        BARP(barid);   // pair: h staging complete (bar.sync drains STS)

        // ---- GEMM2: C2 = h @ W_out + b_out  (1-term h) ----
        float c2[8][4];
#pragma unroll
        for (int j = 0; j < 8; j++) {
            float2 bb = *(const float2*)(b2s + nh + 8 * j + qid * 2);
            c2[j][0] = bb.x; c2[j][1] = bb.y; c2[j][2] = bb.x; c2[j][3] = bb.y;
        }
#pragma unroll
        for (int s = 0; s < 8; s++) {
            uint32_t ao = ((uint32_t)(32 * s) + akadd) ^ axor;
            uint32_t aH[4];
            LDSM4(aH[0], aH[1], aH[2], aH[3], shpH + ao);
            pair_kstep1(c2, aH, sb + SW2, bhl + (((uint32_t)(32 * s) + kl2) ^ xorv));
        }

        // ---- epilogue 2: LayerNorm (quad bfly + pair exchange) + store ----
        float sA = 0.f, qA = 0.f, sB = 0.f, qB = 0.f;
#pragma unroll
        for (int j = 0; j < 8; j++) {
            sA += c2[j][0] + c2[j][1];
            qA += c2[j][0] * c2[j][0] + c2[j][1] * c2[j][1];
            sB += c2[j][2] + c2[j][3];
            qB += c2[j][2] * c2[j][2] + c2[j][3] * c2[j][3];
        }
#pragma unroll
        for (int m = 1; m < 4; m <<= 1) {
            sA += __shfl_xor_sync(0xFFFFFFFFu, sA, m);
            qA += __shfl_xor_sync(0xFFFFFFFFu, qA, m);
            sB += __shfl_xor_sync(0xFFFFFFFFu, sB, m);
            qB += __shfl_xor_sync(0xFFFFFFFFu, qB, m);
        }
        if (qid == 0) {
            *(float4*)(smem + SRED + pair * 256 + half * 128 + quad * 16) =
                make_float4(sA, qA, sB, qB);
        }
        BARP(barid);   // pair: partials visible; also fences h reads before next overwrite
        {
            float4 o = *(const float4*)(smem + SRED + pair * 256 + (half ^ 1) * 128 + quad * 16);
            sA += o.x; qA += o.y; sB += o.z; qB += o.w;
        }
        float mnA = sA * (1.0f / 128.0f);
        float iA = rsqrtf(qA * (1.0f / 128.0f) - mnA * mnA + 1e-5f);
        float mnB = sB * (1.0f / 128.0f);
        float iB = rsqrtf(qB * (1.0f / 128.0f) - mnB * mnB + 1e-5f);

        float* oA = out + (size_t)t * (128 * D) + (size_t)mA * D;
        float* oB = out + (size_t)t * (128 * D) + (size_t)mB * D;
#pragma unroll
        for (int j = 0; j < 8; j++) {
            int n0 = nh + 8 * j + qid * 2;
            float2 g = *(const float2*)(gms + n0);
            float2 b = *(const float2*)(bts + n0);
            float2 rA, rB;
            rA.x = (c2[j][0] - mnA) * iA * g.x + b.x;
            rA.y = (c2[j][1] - mnA) * iA * g.y + b.y;
            rB.x = (c2[j][2] - mnB) * iB * g.x + b.x;
            rB.y = (c2[j][3] - mnB) * iB * g.y + b.y;
            *(float2*)(oA + n0) = rA;
            *(float2*)(oB + n0) = rB;
        }
    }
}

// ===================== launch (single kernel per call) =====================
extern "C" void kernel_launch(void* const* d_in, const int* in_sizes, int n_in,
                              void* d_out, int out_size) {
    const float* x     = (const float*)d_in[0];
    const float* graph = (const float*)d_in[1];
    const float* W_msg = (const float*)d_in[2];
    const float* b_msg = (const float*)d_in[3];
    const float* W_upd = (const float*)d_in[4];
    const float* b_upd = (const float*)d_in[5];
    const float* W_out = (const float*)d_in[6];
    const float* b_out = (const float*)d_in[7];
    const float* gamma = (const float*)d_in[8];
    const float* beta  = (const float*)d_in[9];
    float* out = (float*)d_out;

    cudaFuncSetAttribute(lgn_main, cudaFuncAttributeMaxDynamicSharedMemorySize, SMEM_BYTES);

    lgn_main<<<GRID_MAIN, NTHREADS, SMEM_BYTES>>>(
        x, graph, W_msg, b_msg, W_upd, b_upd, W_out, b_out, gamma, beta, out);
}

// round 16
// speedup vs baseline: 1.4392x; 1.1043x over previous
#include <cuda_runtime.h>
#include <cuda_fp16.h>
#include <cstdint>
#include <math.h>

// ===================== problem constants =====================
#define D 128
#define NROWS (64 * 4096)          // B*T = 262144
#define NTILES (NROWS / 128)       // 2048
#define GRID_MAIN 148
#define NTHREADS 512               // 16 warps = 8 pairs; pair owns 16 rows, warp owns 64 cols

// ===================== helpers =====================
__device__ __forceinline__ uint32_t smem_u32(const void* p) {
    uint32_t a;
    asm("{ .reg .u64 t; cvta.to.shared.u64 t, %1; cvt.u32.u64 %0, t; }" : "=r"(a) : "l"(p));
    return a;
}
__device__ __forceinline__ uint32_t pack2h(__half a, __half b) {
    return (uint32_t)__half_as_ushort(a) | ((uint32_t)__half_as_ushort(b) << 16);
}
__device__ __forceinline__ uint32_t packh2(float a, float b) {
    __half2 h = __floats2half2_rn(a, b);
    return *(uint32_t*)&h;
}
// fp16 two-term split (precompute only)
__device__ __forceinline__ void split2h(float x0, float x1, uint32_t& hi, uint32_t& lo) {
    __half h0 = __float2half_rn(x0), h1 = __float2half_rn(x1);
    hi = pack2h(h0, h1);
    lo = pack2h(__float2half_rn(x0 - __half2float(h0)),
                __float2half_rn(x1 - __half2float(h1)));
}
// tanh-form GELU via sigmoid: 0.5v(1+tanh(u)) = v * sigma(2u); |diff vs exact| <= ~1e-4 rel scale
__device__ __forceinline__ float gelu_fast(float v) {
    return v / (1.0f + __expf(-1.5957691216057308f * v * (1.0f + 0.044715f * v * v)));
}

#define MMA(c0, c1, c2, c3, a0, a1, a2, a3, b0, b1)                                   \
    asm volatile("mma.sync.aligned.m16n8k16.row.col.f32.f16.f16.f32 "                 \
                 "{%0,%1,%2,%3}, {%4,%5,%6,%7}, {%8,%9}, {%0,%1,%2,%3};"              \
                 : "+f"(c0), "+f"(c1), "+f"(c2), "+f"(c3)                             \
                 : "r"(a0), "r"(a1), "r"(a2), "r"(a3), "r"(b0), "r"(b1))

#define LDSM4(r0, r1, r2, r3, addr)                                                    \
    asm volatile("ldmatrix.sync.aligned.m8n8.x4.shared.b16 {%0,%1,%2,%3}, [%4];"       \
                 : "=r"(r0), "=r"(r1), "=r"(r2), "=r"(r3) : "r"(addr))

// named barrier for a 64-thread pair (ids 1..8)
#define BARP(id) asm volatile("bar.sync %0, 64;" :: "r"(id) : "memory")

// ===================== SMEM map =====================
// Weight images: [n][k] fp16, 256B rows, XOR-swizzled 16B chunks (conflict-free ldmatrix)
#define SW1  0          // W1 image (32 KB); Wb during precompute
#define SW2  32768      // W_out image (32 KB); T1 during precompute
#define SHH  65536      // h staging: 8 pairs * 4 KB (16 rows x 256B, A layout)
#define SB1  98304      // b1
#define SB2  98816      // b_out
#define SGAM 99328      // gamma (bg during precompute)
#define SBET 99840      // beta
#define SRED 100352     // 2 KB: LN pair partials / bg scratch
#define SMEM_BYTES 102400

// Precompute k-step: 2-term fp16 (A split hi/lo, B single). 4 B-LDSM4 then 16 MMAs.
__device__ __forceinline__ void pair_kstep2(float (&c)[8][4],
                                            const uint32_t* aH, const uint32_t* aL,
                                            uint32_t base, uint32_t sAdd) {
    uint32_t b[4][4];
#pragma unroll
    for (int j = 0; j < 4; j++)
        LDSM4(b[j][0], b[j][1], b[j][2], b[j][3], base + j * 4096 + sAdd);
#pragma unroll
    for (int j = 0; j < 4; j++) {
        MMA(c[2 * j][0], c[2 * j][1], c[2 * j][2], c[2 * j][3],
            aH[0], aH[1], aH[2], aH[3], b[j][0], b[j][1]);
        MMA(c[2 * j + 1][0], c[2 * j + 1][1], c[2 * j + 1][2], c[2 * j + 1][3],
            aH[0], aH[1], aH[2], aH[3], b[j][2], b[j][3]);
    }
#pragma unroll
    for (int j = 0; j < 4; j++) {
        MMA(c[2 * j][0], c[2 * j][1], c[2 * j][2], c[2 * j][3],
            aL[0], aL[1], aL[2], aL[3], b[j][0], b[j][1]);
        MMA(c[2 * j + 1][0], c[2 * j + 1][1], c[2 * j + 1][2], c[2 * j + 1][3],
            aL[0], aL[1], aL[2], aL[3], b[j][2], b[j][3]);
    }
}

// 1-term main-loop k-step (A single fp16): 4 B-LDSM4 then 8 MMAs.
__device__ __forceinline__ void pair_kstep1(float (&c)[8][4], const uint32_t* aH,
                                            uint32_t base, uint32_t sAdd) {
    uint32_t b[4][4];
#pragma unroll
    for (int j = 0; j < 4; j++)
        LDSM4(b[j][0], b[j][1], b[j][2], b[j][3], base + j * 4096 + sAdd);
#pragma unroll
    for (int j = 0; j < 4; j++) {
        MMA(c[2 * j][0], c[2 * j][1], c[2 * j][2], c[2 * j][3],
            aH[0], aH[1], aH[2], aH[3], b[j][0], b[j][1]);
        MMA(c[2 * j + 1][0], c[2 * j + 1][1], c[2 * j + 1][2], c[2 * j + 1][3],
            aH[0], aH[1], aH[2], aH[3], b[j][2], b[j][3]);
    }
}

// A fragments (16 rows x k16) from a global fp32 row pointer, 2-term (precompute only)
__device__ __forceinline__ void load_a_frags(const float* arow, int s,
                                             uint32_t (&aH)[4], uint32_t (&aL)[4]) {
    float2 v00 = *(const float2*)(arow + 16 * s);
    float2 v10 = *(const float2*)(arow + 16 * s + 8 * D);
    float2 v01 = *(const float2*)(arow + 16 * s + 8);
    float2 v11 = *(const float2*)(arow + 16 * s + 8 * D + 8);
    split2h(v00.x, v00.y, aH[0], aL[0]);
    split2h(v10.x, v10.y, aH[1], aL[1]);
    split2h(v01.x, v01.y, aH[2], aL[2]);
    split2h(v11.x, v11.y, aH[3], aL[3]);
}

// A fragments, single fp16 (main loop)
__device__ __forceinline__ void load_a_frags1(const float* arow, int s, uint32_t (&aH)[4]) {
    float2 v00 = *(const float2*)(arow + 16 * s);
    float2 v10 = *(const float2*)(arow + 16 * s + 8 * D);
    float2 v01 = *(const float2*)(arow + 16 * s + 8);
    float2 v11 = *(const float2*)(arow + 16 * s + 8 * D + 8);
    aH[0] = packh2(v00.x, v00.y);
    aH[1] = packh2(v10.x, v10.y);
    aH[2] = packh2(v01.x, v01.y);
    aH[3] = packh2(v11.x, v11.y);
}

// Store one fp32 value into a single-fp16 B-image ([n][k] layout, XOR swizzle) at (k=m, n).
__device__ __forceinline__ void store_bimg(char* smem, uint32_t dst, int m, int n, float v) {
    uint32_t off = ((uint32_t)(n * 256 + m * 2)) ^ (((uint32_t)n & 7u) << 4);
    *(__half*)(smem + dst + off) = __float2half_rn(v);
}

// ===================== single fused kernel =====================
__global__ void __launch_bounds__(NTHREADS, 1)
lgn_main(const float* __restrict__ x, const float* __restrict__ graph,
         const float* __restrict__ W_msg, const float* __restrict__ b_msg,
         const float* __restrict__ W_upd, const float* __restrict__ b_upd,
         const float* __restrict__ Wout, const float* __restrict__ bout,
         const float* __restrict__ gamma, const float* __restrict__ beta,
         float* __restrict__ out) {
    extern __shared__ char smem[];
    const uint32_t sb = smem_u32(smem);
    const int tid = threadIdx.x;
    const int wid = tid >> 5;
    const int l = tid & 31;
    const int pair = wid >> 1;     // 0..7: owns rows [16*pair, 16*pair+16)
    const int half = wid & 1;      // 0: cols 0-63, 1: cols 64-127
    const int quad = l >> 2;
    const int qid = l & 3;
    const int mA = pair * 16 + quad;
    const int mB = mA + 8;
    const int nh = half * 64;

    // B-image ldmatrix lane constants
    const uint32_t nlane = ((l >> 4) & 1) * 8 + (l & 7);
    const uint32_t laneN = nlane * 256;
    const uint32_t xorv  = (nlane & 7) << 4;
    const uint32_t kl2   = ((l >> 3) & 1) * 16;
    const uint32_t bhl   = (uint32_t)half * 16384 + laneN;   // half col offset + lane row

    // h-staging (A-image) lane constants
    const uint32_t arow  = (l & 7) + ((l >> 3) & 1) * 8;
    const uint32_t akadd = ((l >> 4) & 1) * 16;
    const uint32_t axor  = (l & 7) << 4;
    const uint32_t shpH  = sb + SHH + pair * 4096 + arow * 256;
    char* hwH = smem + SHH + pair * 4096;   // write side (by row)
    const int barid = pair + 1;

    // =========================================================================
    // In-kernel precompute (2-term A throughout for accuracy):
    //   T1 = graph @ W_upd[128:], W1 = W_upd[:128] + W_msg @ T1
    //   bg = b_msg @ graph,       b1 = b_upd + bg @ W_upd[128:]
    // =========================================================================

    // ---- P0: stage Wb = W_upd[128:] as B image into SW1; bg quarter sums ----
    for (int idx = tid; idx < D * D; idx += NTHREADS) {
        int k = idx >> 7, n = idx & 127;
        store_bimg(smem, SW1, k, n, W_upd[(D + k) * D + n]);
    }
    {
        int j = tid & 127, hh = tid >> 7;   // hh in 0..3
        float p = 0.f;
#pragma unroll 8
        for (int g = hh * 32; g < hh * 32 + 32; g++)
            p += b_msg[g] * graph[g * D + j];
        ((float*)(smem + SRED))[tid] = p;
    }
    __syncthreads();
    if (tid < D) {
        const float* sr = (const float*)(smem + SRED);
        ((float*)(smem + SGAM))[tid] = sr[tid] + sr[tid + 128] + sr[tid + 256] + sr[tid + 384];
    }

    // ---- P1: T1 = graph @ Wb ; write T1^T -> SW2 B-image ----
    {
        float c[8][4];
#pragma unroll
        for (int j = 0; j < 8; j++) { c[j][0] = c[j][1] = c[j][2] = c[j][3] = 0.f; }
        const float* ar = graph + (size_t)mA * D + qid * 2;
#pragma unroll
        for (int s = 0; s < 8; s++) {
            uint32_t aH[4], aL[4];
            load_a_frags(ar, s, aH, aL);
            pair_kstep2(c, aH, aL, sb + SW1, bhl + (((uint32_t)(32 * s) + kl2) ^ xorv));
        }
#pragma unroll
        for (int j = 0; j < 8; j++) {
            int n0 = nh + 8 * j + qid * 2;
            store_bimg(smem, SW2, mA, n0,     c[j][0]);
            store_bimg(smem, SW2, mA, n0 + 1, c[j][1]);
            store_bimg(smem, SW2, mB, n0,     c[j][2]);
            store_bimg(smem, SW2, mB, n0 + 1, c[j][3]);
        }
    }
    __syncthreads();

    // ---- P2: W1 = W_upd[:128] + W_msg @ T1 ; write -> SW1 B-image ----
    {
        float c[8][4];
#pragma unroll
        for (int j = 0; j < 8; j++) { c[j][0] = c[j][1] = c[j][2] = c[j][3] = 0.f; }
        const float* ar = W_msg + (size_t)mA * D + qid * 2;
#pragma unroll
        for (int s = 0; s < 8; s++) {
            uint32_t aH[4], aL[4];
            load_a_frags(ar, s, aH, aL);
            pair_kstep2(c, aH, aL, sb + SW2, bhl + (((uint32_t)(32 * s) + kl2) ^ xorv));
        }
#pragma unroll
        for (int j = 0; j < 8; j++) {   // += W_upd top half
            int n0 = nh + 8 * j + qid * 2;
            float2 tA = *(const float2*)(W_upd + (size_t)mA * D + n0);
            float2 tB = *(const float2*)(W_upd + (size_t)mB * D + n0);
            c[j][0] += tA.x; c[j][1] += tA.y; c[j][2] += tB.x; c[j][3] += tB.y;
        }
        // SW1 (Wb) dead after P1's sync -> safe to overwrite
#pragma unroll
        for (int j = 0; j < 8; j++) {
            int n0 = nh + 8 * j + qid * 2;
            store_bimg(smem, SW1, mA, n0,     c[j][0]);
            store_bimg(smem, SW1, mA, n0 + 1, c[j][1]);
            store_bimg(smem, SW1, mB, n0,     c[j][2]);
            store_bimg(smem, SW1, mB, n0 + 1, c[j][3]);
        }
    }
    __syncthreads();

    // ---- P3: stage W_out -> SW2 (T1 dead); b1 from bg; final vectors ----
    for (int idx = tid; idx < D * D; idx += NTHREADS) {
        int k = idx >> 7, n = idx & 127;
        store_bimg(smem, SW2, k, n, Wout[k * D + n]);
    }
    if (tid < D) {
        const float* bgv = (const float*)(smem + SGAM);
        float acc = b_upd[tid];
#pragma unroll 8
        for (int h = 0; h < D; h++)
            acc += bgv[h] * W_upd[(D + h) * D + tid];
        ((float*)(smem + SB1))[tid] = acc;
    }
    __syncthreads();
    if (tid < D) {
        ((float*)(smem + SB2))[tid]  = bout[tid];
        ((float*)(smem + SGAM))[tid] = gamma[tid];
        ((float*)(smem + SBET))[tid] = beta[tid];
    }
    __syncthreads();

    const float* b1s = (const float*)(smem + SB1);
    const float* b2s = (const float*)(smem + SB2);
    const float* gms = (const float*)(smem + SGAM);
    const float* bts = (const float*)(smem + SBET);

    // =========================================================================
    // Main loop: per 128-row tile:  y = LN( gelu(x@W1 + b1) @ W2 + b2 )
    // =========================================================================
    for (int t = blockIdx.x; t < NTILES; t += gridDim.x) {
        const float* xrow = x + (size_t)t * (128 * D) + (size_t)mA * D + qid * 2;

        // ---- GEMM1: C1 = x @ W1 + b1  (warp's 64-col half; single-fp16 x) ----
        float c1[8][4];
#pragma unroll
        for (int j = 0; j < 8; j++) {
            float2 bb = *(const float2*)(b1s + nh + 8 * j + qid * 2);
            c1[j][0] = bb.x; c1[j][1] = bb.y; c1[j][2] = bb.x; c1[j][3] = bb.y;
        }
#pragma unroll
        for (int s = 0; s < 8; s++) {
            uint32_t aH[4];
            load_a_frags1(xrow, s, aH);
            pair_kstep1(c1, aH, sb + SW1, bhl + (((uint32_t)(32 * s) + kl2) ^ xorv));
        }

        // ---- epilogue 1: fast GELU, single-fp16 pack, stage h (warp's k-half) ----
#pragma unroll
        for (int j = 0; j < 8; j++) {
            uint32_t kb = (uint32_t)(half * 128 + 16 * j + 4 * qid);
            uint32_t hA = packh2(gelu_fast(c1[j][0]), gelu_fast(c1[j][1]));
            uint32_t hB = packh2(gelu_fast(c1[j][2]), gelu_fast(c1[j][3]));
            uint32_t sw = kb ^ ((uint32_t)quad << 4);
            *(uint32_t*)(hwH + (uint32_t)quad * 256 + sw) = hA;
            *(uint32_t*)(hwH + (uint32_t)(quad + 8) * 256 + sw) = hB;
        }
        BARP(barid);   // pair: h staging complete (bar.sync drains STS)

        // ---- GEMM2: C2 = h @ W_out + b_out  (1-term h) ----
        float c2[8][4];
#pragma unroll
        for (int j = 0; j < 8; j++) {
            float2 bb = *(const float2*)(b2s + nh + 8 * j + qid * 2);
            c2[j][0] = bb.x; c2[j][1] = bb.y; c2[j][2] = bb.x; c2[j][3] = bb.y;
        }
#pragma unroll
        for (int s = 0; s < 8; s++) {
            uint32_t ao = ((uint32_t)(32 * s) + akadd) ^ axor;
            uint32_t aH[4];
            LDSM4(aH[0], aH[1], aH[2], aH[3], shpH + ao);
            pair_kstep1(c2, aH, sb + SW2, bhl + (((uint32_t)(32 * s) + kl2) ^ xorv));
        }

        // ---- epilogue 2: LayerNorm (quad bfly + pair exchange) + store ----
        float sA = 0.f, qA = 0.f, sB = 0.f, qB = 0.f;
#pragma unroll
        for (int j = 0; j < 8; j++) {
            sA += c2[j][0] + c2[j][1];
            qA += c2[j][0] * c2[j][0] + c2[j][1] * c2[j][1];
            sB += c2[j][2] + c2[j][3];
            qB += c2[j][2] * c2[j][2] + c2[j][3] * c2[j][3];
        }
#pragma unroll
        for (int m = 1; m < 4; m <<= 1) {
            sA += __shfl_xor_sync(0xFFFFFFFFu, sA, m);
            qA += __shfl_xor_sync(0xFFFFFFFFu, qA, m);
            sB += __shfl_xor_sync(0xFFFFFFFFu, sB, m);
            qB += __shfl_xor_sync(0xFFFFFFFFu, qB, m);
        }
        if (qid == 0) {
            *(float4*)(smem + SRED + pair * 256 + half * 128 + quad * 16) =
                make_float4(sA, qA, sB, qB);
        }
        BARP(barid);   // pair: partials visible; also fences h reads before next overwrite
        {
            float4 o = *(const float4*)(smem + SRED + pair * 256 + (half ^ 1) * 128 + quad * 16);
            sA += o.x; qA += o.y; sB += o.z; qB += o.w;
        }
        float mnA = sA * (1.0f / 128.0f);
        float iA = rsqrtf(qA * (1.0f / 128.0f) - mnA * mnA + 1e-5f);
        float mnB = sB * (1.0f / 128.0f);
        float iB = rsqrtf(qB * (1.0f / 128.0f) - mnB * mnB + 1e-5f);

        float* oA = out + (size_t)t * (128 * D) + (size_t)mA * D;
        float* oB = out + (size_t)t * (128 * D) + (size_t)mB * D;
#pragma unroll
        for (int j = 0; j < 8; j++) {
            int n0 = nh + 8 * j + qid * 2;
            float2 g = *(const float2*)(gms + n0);
            float2 b = *(const float2*)(bts + n0);
            float2 rA, rB;
            rA.x = (c2[j][0] - mnA) * iA * g.x + b.x;
            rA.y = (c2[j][1] - mnA) * iA * g.y + b.y;
            rB.x = (c2[j][2] - mnB) * iB * g.x + b.x;
            rB.y = (c2[j][3] - mnB) * iB * g.y + b.y;
            *(float2*)(oA + n0) = rA;
            *(float2*)(oB + n0) = rB;
        }
    }
}

// ===================== launch (single kernel per call) =====================
extern "C" void kernel_launch(void* const* d_in, const int* in_sizes, int n_in,
                              void* d_out, int out_size) {
    const float* x     = (const float*)d_in[0];
    const float* graph = (const float*)d_in[1];
    const float* W_msg = (const float*)d_in[2];
    const float* b_msg = (const float*)d_in[3];
    const float* W_upd = (const float*)d_in[4];
    const float* b_upd = (const float*)d_in[5];
    const float* W_out = (const float*)d_in[6];
    const float* b_out = (const float*)d_in[7];
    const float* gamma = (const float*)d_in[8];
    const float* beta  = (const float*)d_in[9];
    float* out = (float*)d_out;

    cudaFuncSetAttribute(lgn_main, cudaFuncAttributeMaxDynamicSharedMemorySize, SMEM_BYTES);

    lgn_main<<<GRID_MAIN, NTHREADS, SMEM_BYTES>>>(
        x, graph, W_msg, b_msg, W_upd, b_upd, W_out, b_out, gamma, beta, out);
}

// round 17
// speedup vs baseline: 1.5885x; 1.1037x over previous
#include <cuda_runtime.h>
#include <cuda_fp16.h>
#include <cstdint>
#include <math.h>

// ===================== problem constants =====================
#define D 128
#define NROWS (64 * 4096)          // B*T = 262144
#define NTILES (NROWS / 128)       // 2048
#define GRID_MAIN 148
#define NTHREADS 512               // 16 warps = 8 pairs; pair owns 16 rows, warp owns 64 cols

// ===================== helpers =====================
__device__ __forceinline__ uint32_t smem_u32(const void* p) {
    uint32_t a;
    asm("{ .reg .u64 t; cvta.to.shared.u64 t, %1; cvt.u32.u64 %0, t; }" : "=r"(a) : "l"(p));
    return a;
}
__device__ __forceinline__ uint32_t pack2h(__half a, __half b) {
    return (uint32_t)__half_as_ushort(a) | ((uint32_t)__half_as_ushort(b) << 16);
}
__device__ __forceinline__ uint32_t packh2(float a, float b) {
    __half2 h = __floats2half2_rn(a, b);
    return *(uint32_t*)&h;
}
// fp16 two-term split (precompute only)
__device__ __forceinline__ void split2h(float x0, float x1, uint32_t& hi, uint32_t& lo) {
    __half h0 = __float2half_rn(x0), h1 = __float2half_rn(x1);
    hi = pack2h(h0, h1);
    lo = pack2h(__float2half_rn(x0 - __half2float(h0)),
                __float2half_rn(x1 - __half2float(h1)));
}
// tanh-form GELU via sigmoid: 0.5v(1+tanh(u)) = v * sigma(2u)
__device__ __forceinline__ float gelu_fast(float v) {
    return v / (1.0f + __expf(-1.5957691216057308f * v * (1.0f + 0.044715f * v * v)));
}

#define MMA(c0, c1, c2, c3, a0, a1, a2, a3, b0, b1)                                   \
    asm volatile("mma.sync.aligned.m16n8k16.row.col.f32.f16.f16.f32 "                 \
                 "{%0,%1,%2,%3}, {%4,%5,%6,%7}, {%8,%9}, {%0,%1,%2,%3};"              \
                 : "+f"(c0), "+f"(c1), "+f"(c2), "+f"(c3)                             \
                 : "r"(a0), "r"(a1), "r"(a2), "r"(a3), "r"(b0), "r"(b1))

#define LDSM4(r0, r1, r2, r3, addr)                                                    \
    asm volatile("ldmatrix.sync.aligned.m8n8.x4.shared.b16 {%0,%1,%2,%3}, [%4];"       \
                 : "=r"(r0), "=r"(r1), "=r"(r2), "=r"(r3) : "r"(addr))

// named barrier for a 64-thread pair (ids 1..8)
#define BARP(id) asm volatile("bar.sync %0, 64;" :: "r"(id) : "memory")

// ===================== SMEM map =====================
// Weight images: [n][k] fp16, 256B rows, XOR-swizzled 16B chunks (conflict-free ldmatrix)
#define SW1  0          // W1 image (32 KB); Wb during precompute
#define SW2  32768      // W_out image (32 KB); T1 during precompute
#define SX   65536      // x staging: 8 pairs * 4 KB (16 rows x 256B, A layout)
#define SHH  98304      // h staging: 8 pairs * 4 KB
#define SB1  131072     // b1
#define SB2  131584     // b_out
#define SGAM 132096     // gamma (bg during precompute)
#define SBET 132608     // beta
#define SRED 133120     // 2 KB: LN pair partials / bg scratch
#define SMEM_BYTES 135168

// Precompute k-step: 2-term fp16 (A split hi/lo, B single). 4 B-LDSM4 then 16 MMAs.
__device__ __forceinline__ void pair_kstep2(float (&c)[8][4],
                                            const uint32_t* aH, const uint32_t* aL,
                                            uint32_t base, uint32_t sAdd) {
    uint32_t b[4][4];
#pragma unroll
    for (int j = 0; j < 4; j++)
        LDSM4(b[j][0], b[j][1], b[j][2], b[j][3], base + j * 4096 + sAdd);
#pragma unroll
    for (int j = 0; j < 4; j++) {
        MMA(c[2 * j][0], c[2 * j][1], c[2 * j][2], c[2 * j][3],
            aH[0], aH[1], aH[2], aH[3], b[j][0], b[j][1]);
        MMA(c[2 * j + 1][0], c[2 * j + 1][1], c[2 * j + 1][2], c[2 * j + 1][3],
            aH[0], aH[1], aH[2], aH[3], b[j][2], b[j][3]);
    }
#pragma unroll
    for (int j = 0; j < 4; j++) {
        MMA(c[2 * j][0], c[2 * j][1], c[2 * j][2], c[2 * j][3],
            aL[0], aL[1], aL[2], aL[3], b[j][0], b[j][1]);
        MMA(c[2 * j + 1][0], c[2 * j + 1][1], c[2 * j + 1][2], c[2 * j + 1][3],
            aL[0], aL[1], aL[2], aL[3], b[j][2], b[j][3]);
    }
}

// 1-term main-loop k-step (A single fp16): 4 B-LDSM4 then 8 MMAs.
__device__ __forceinline__ void pair_kstep1(float (&c)[8][4], const uint32_t* aH,
                                            uint32_t base, uint32_t sAdd) {
    uint32_t b[4][4];
#pragma unroll
    for (int j = 0; j < 4; j++)
        LDSM4(b[j][0], b[j][1], b[j][2], b[j][3], base + j * 4096 + sAdd);
#pragma unroll
    for (int j = 0; j < 4; j++) {
        MMA(c[2 * j][0], c[2 * j][1], c[2 * j][2], c[2 * j][3],
            aH[0], aH[1], aH[2], aH[3], b[j][0], b[j][1]);
        MMA(c[2 * j + 1][0], c[2 * j + 1][1], c[2 * j + 1][2], c[2 * j + 1][3],
            aH[0], aH[1], aH[2], aH[3], b[j][2], b[j][3]);
    }
}

// A fragments (16 rows x k16) from a global fp32 row pointer, 2-term (precompute only)
__device__ __forceinline__ void load_a_frags(const float* arow, int s,
                                             uint32_t (&aH)[4], uint32_t (&aL)[4]) {
    float2 v00 = *(const float2*)(arow + 16 * s);
    float2 v10 = *(const float2*)(arow + 16 * s + 8 * D);
    float2 v01 = *(const float2*)(arow + 16 * s + 8);
    float2 v11 = *(const float2*)(arow + 16 * s + 8 * D + 8);
    split2h(v00.x, v00.y, aH[0], aL[0]);
    split2h(v10.x, v10.y, aH[1], aL[1]);
    split2h(v01.x, v01.y, aH[2], aL[2]);
    split2h(v11.x, v11.y, aH[3], aL[3]);
}

// Store one fp32 value into a single-fp16 B-image ([n][k] layout, XOR swizzle) at (k=m, n).
__device__ __forceinline__ void store_bimg(char* smem, uint32_t dst, int m, int n, float v) {
    uint32_t off = ((uint32_t)(n * 256 + m * 2)) ^ (((uint32_t)n & 7u) << 4);
    *(__half*)(smem + dst + off) = __float2half_rn(v);
}

// ===================== single fused kernel =====================
__global__ void __launch_bounds__(NTHREADS, 1)
lgn_main(const float* __restrict__ x, const float* __restrict__ graph,
         const float* __restrict__ W_msg, const float* __restrict__ b_msg,
         const float* __restrict__ W_upd, const float* __restrict__ b_upd,
         const float* __restrict__ Wout, const float* __restrict__ bout,
         const float* __restrict__ gamma, const float* __restrict__ beta,
         float* __restrict__ out) {
    extern __shared__ char smem[];
    const uint32_t sb = smem_u32(smem);
    const int tid = threadIdx.x;
    const int wid = tid >> 5;
    const int l = tid & 31;
    const int pair = wid >> 1;     // 0..7: owns rows [16*pair, 16*pair+16)
    const int half = wid & 1;      // 0: cols 0-63, 1: cols 64-127
    const int quad = l >> 2;
    const int qid = l & 3;
    const int mA = pair * 16 + quad;
    const int mB = mA + 8;
    const int nh = half * 64;

    // B-image ldmatrix lane constants
    const uint32_t nlane = ((l >> 4) & 1) * 8 + (l & 7);
    const uint32_t laneN = nlane * 256;
    const uint32_t xorv  = (nlane & 7) << 4;
    const uint32_t kl2   = ((l >> 3) & 1) * 16;
    const uint32_t bhl   = (uint32_t)half * 16384 + laneN;   // half col offset + lane row

    // A-image ldmatrix lane constants (x and h staging)
    const uint32_t arow  = (l & 7) + ((l >> 3) & 1) * 8;
    const uint32_t akadd = ((l >> 4) & 1) * 16;
    const uint32_t axor  = (l & 7) << 4;
    const uint32_t sxp   = sb + SX  + pair * 4096 + arow * 256;
    const uint32_t shpH  = sb + SHH + pair * 4096 + arow * 256;
    char* xw  = smem + SX  + pair * 4096;   // x write side
    char* hwH = smem + SHH + pair * 4096;   // h write side (by row)
    const int barid = pair + 1;
    const int ip = half * 32 + l;           // 0..63 within pair (x staging role)

    // =========================================================================
    // In-kernel precompute (2-term A throughout for accuracy):
    //   T1 = graph @ W_upd[128:], W1 = W_upd[:128] + W_msg @ T1
    //   bg = b_msg @ graph,       b1 = b_upd + bg @ W_upd[128:]
    // =========================================================================

    // ---- P0: stage Wb = W_upd[128:] as B image into SW1; bg quarter sums ----
    for (int idx = tid; idx < D * D; idx += NTHREADS) {
        int k = idx >> 7, n = idx & 127;
        store_bimg(smem, SW1, k, n, W_upd[(D + k) * D + n]);
    }
    {
        int j = tid & 127, hh = tid >> 7;   // hh in 0..3
        float p = 0.f;
#pragma unroll 8
        for (int g = hh * 32; g < hh * 32 + 32; g++)
            p += b_msg[g] * graph[g * D + j];
        ((float*)(smem + SRED))[tid] = p;
    }
    __syncthreads();
    if (tid < D) {
        const float* sr = (const float*)(smem + SRED);
        ((float*)(smem + SGAM))[tid] = sr[tid] + sr[tid + 128] + sr[tid + 256] + sr[tid + 384];
    }

    // ---- P1: T1 = graph @ Wb ; write T1^T -> SW2 B-image ----
    {
        float c[8][4];
#pragma unroll
        for (int j = 0; j < 8; j++) { c[j][0] = c[j][1] = c[j][2] = c[j][3] = 0.f; }
        const float* ar = graph + (size_t)mA * D + qid * 2;
#pragma unroll
        for (int s = 0; s < 8; s++) {
            uint32_t aH[4], aL[4];
            load_a_frags(ar, s, aH, aL);
            pair_kstep2(c, aH, aL, sb + SW1, bhl + (((uint32_t)(32 * s) + kl2) ^ xorv));
        }
#pragma unroll
        for (int j = 0; j < 8; j++) {
            int n0 = nh + 8 * j + qid * 2;
            store_bimg(smem, SW2, mA, n0,     c[j][0]);
            store_bimg(smem, SW2, mA, n0 + 1, c[j][1]);
            store_bimg(smem, SW2, mB, n0,     c[j][2]);
            store_bimg(smem, SW2, mB, n0 + 1, c[j][3]);
        }
    }
    __syncthreads();

    // ---- P2: W1 = W_upd[:128] + W_msg @ T1 ; write -> SW1 B-image ----
    {
        float c[8][4];
#pragma unroll
        for (int j = 0; j < 8; j++) { c[j][0] = c[j][1] = c[j][2] = c[j][3] = 0.f; }
        const float* ar = W_msg + (size_t)mA * D + qid * 2;
#pragma unroll
        for (int s = 0; s < 8; s++) {
            uint32_t aH[4], aL[4];
            load_a_frags(ar, s, aH, aL);
            pair_kstep2(c, aH, aL, sb + SW2, bhl + (((uint32_t)(32 * s) + kl2) ^ xorv));
        }
#pragma unroll
        for (int j = 0; j < 8; j++) {   // += W_upd top half
            int n0 = nh + 8 * j + qid * 2;
            float2 tA = *(const float2*)(W_upd + (size_t)mA * D + n0);
            float2 tB = *(const float2*)(W_upd + (size_t)mB * D + n0);
            c[j][0] += tA.x; c[j][1] += tA.y; c[j][2] += tB.x; c[j][3] += tB.y;
        }
        // SW1 (Wb) dead after P1's sync -> safe to overwrite
#pragma unroll
        for (int j = 0; j < 8; j++) {
            int n0 = nh + 8 * j + qid * 2;
            store_bimg(smem, SW1, mA, n0,     c[j][0]);
            store_bimg(smem, SW1, mA, n0 + 1, c[j][1]);
            store_bimg(smem, SW1, mB, n0,     c[j][2]);
            store_bimg(smem, SW1, mB, n0 + 1, c[j][3]);
        }
    }
    __syncthreads();

    // ---- P3: stage W_out -> SW2 (T1 dead); b1 from bg; final vectors ----
    for (int idx = tid; idx < D * D; idx += NTHREADS) {
        int k = idx >> 7, n = idx & 127;
        store_bimg(smem, SW2, k, n, Wout[k * D + n]);
    }
    if (tid < D) {
        const float* bgv = (const float*)(smem + SGAM);
        float acc = b_upd[tid];
#pragma unroll 8
        for (int h = 0; h < D; h++)
            acc += bgv[h] * W_upd[(D + h) * D + tid];
        ((float*)(smem + SB1))[tid] = acc;
    }
    __syncthreads();
    if (tid < D) {
        ((float*)(smem + SB2))[tid]  = bout[tid];
        ((float*)(smem + SGAM))[tid] = gamma[tid];
        ((float*)(smem + SBET))[tid] = beta[tid];
    }
    __syncthreads();

    const float* b1s = (const float*)(smem + SB1);
    const float* b2s = (const float*)(smem + SB2);
    const float* gms = (const float*)(smem + SGAM);
    const float* bts = (const float*)(smem + SBET);

    // =========================================================================
    // Main loop: per 128-row tile:  y = LN( gelu(x@W1 + b1) @ W2 + b2 )
    // =========================================================================
    for (int t = blockIdx.x; t < NTILES; t += gridDim.x) {
        // ---- stage x (pair's 16 rows) into fp16 A-image; coalesced LDG.128 ----
        {
            const float4* xp = (const float4*)(x + (size_t)t * (128 * D) +
                                               (size_t)pair * 16 * D);
#pragma unroll
            for (int k = 0; k < 8; k++) {
                int f = ip + 64 * k;                 // float4 index in 16x128 tile
                float4 v = xp[f];
                int row = f >> 5;
                uint32_t off = (uint32_t)(row * 256) +
                               (((uint32_t)((f & 31) * 8)) ^ (((uint32_t)row & 7u) << 4));
                *(uint2*)(xw + off) = make_uint2(packh2(v.x, v.y), packh2(v.z, v.w));
            }
        }
        BARP(barid);   // pair: x image ready (bar.sync drains STS)

        // ---- GEMM1: C1 = x @ W1 + b1  (warp's 64-col half; A via LDSM) ----
        float c1[8][4];
#pragma unroll
        for (int j = 0; j < 8; j++) {
            float2 bb = *(const float2*)(b1s + nh + 8 * j + qid * 2);
            c1[j][0] = bb.x; c1[j][1] = bb.y; c1[j][2] = bb.x; c1[j][3] = bb.y;
        }
#pragma unroll
        for (int s = 0; s < 8; s++) {
            uint32_t aH[4];
            LDSM4(aH[0], aH[1], aH[2], aH[3], sxp + (((uint32_t)(32 * s) + akadd) ^ axor));
            pair_kstep1(c1, aH, sb + SW1, bhl + (((uint32_t)(32 * s) + kl2) ^ xorv));
        }

        // ---- epilogue 1: fast GELU, single-fp16 pack, stage h (warp's k-half) ----
#pragma unroll
        for (int j = 0; j < 8; j++) {
            uint32_t kb = (uint32_t)(half * 128 + 16 * j + 4 * qid);
            uint32_t hA = packh2(gelu_fast(c1[j][0]), gelu_fast(c1[j][1]));
            uint32_t hB = packh2(gelu_fast(c1[j][2]), gelu_fast(c1[j][3]));
            uint32_t sw = kb ^ ((uint32_t)quad << 4);
            *(uint32_t*)(hwH + (uint32_t)quad * 256 + sw) = hA;
            *(uint32_t*)(hwH + (uint32_t)(quad + 8) * 256 + sw) = hB;
        }
        BARP(barid);   // pair: h staging complete

        // ---- GEMM2: C2 = h @ W_out + b_out  (1-term h) ----
        float c2[8][4];
#pragma unroll
        for (int j = 0; j < 8; j++) {
            float2 bb = *(const float2*)(b2s + nh + 8 * j + qid * 2);
            c2[j][0] = bb.x; c2[j][1] = bb.y; c2[j][2] = bb.x; c2[j][3] = bb.y;
        }
#pragma unroll
        for (int s = 0; s < 8; s++) {
            uint32_t aH[4];
            LDSM4(aH[0], aH[1], aH[2], aH[3], shpH + (((uint32_t)(32 * s) + akadd) ^ axor));
            pair_kstep1(c2, aH, sb + SW2, bhl + (((uint32_t)(32 * s) + kl2) ^ xorv));
        }

        // ---- epilogue 2: LayerNorm (quad bfly + pair exchange) + store ----
        float sA = 0.f, qA = 0.f, sB = 0.f, qB = 0.f;
#pragma unroll
        for (int j = 0; j < 8; j++) {
            sA += c2[j][0] + c2[j][1];
            qA += c2[j][0] * c2[j][0] + c2[j][1] * c2[j][1];
            sB += c2[j][2] + c2[j][3];
            qB += c2[j][2] * c2[j][2] + c2[j][3] * c2[j][3];
        }
#pragma unroll
        for (int m = 1; m < 4; m <<= 1) {
            sA += __shfl_xor_sync(0xFFFFFFFFu, sA, m);
            qA += __shfl_xor_sync(0xFFFFFFFFu, qA, m);
            sB += __shfl_xor_sync(0xFFFFFFFFu, sB, m);
            qB += __shfl_xor_sync(0xFFFFFFFFu, qB, m);
        }
        if (qid == 0) {
            *(float4*)(smem + SRED + pair * 256 + half * 128 + quad * 16) =
                make_float4(sA, qA, sB, qB);
        }
        BARP(barid);   // pair: partials visible; also fences x/h reads before next overwrite
        {
            float4 o = *(const float4*)(smem + SRED + pair * 256 + (half ^ 1) * 128 + quad * 16);
            sA += o.x; qA += o.y; sB += o.z; qB += o.w;
        }
        float mnA = sA * (1.0f / 128.0f);
        float iA = rsqrtf(qA * (1.0f / 128.0f) - mnA * mnA + 1e-5f);
        float mnB = sB * (1.0f / 128.0f);
        float iB = rsqrtf(qB * (1.0f / 128.0f) - mnB * mnB + 1e-5f);

        float* oA = out + (size_t)t * (128 * D) + (size_t)mA * D;
        float* oB = out + (size_t)t * (128 * D) + (size_t)mB * D;
#pragma unroll
        for (int j = 0; j < 8; j++) {
            int n0 = nh + 8 * j + qid * 2;
            float2 g = *(const float2*)(gms + n0);
            float2 b = *(const float2*)(bts + n0);
            float2 rA, rB;
            rA.x = (c2[j][0] - mnA) * iA * g.x + b.x;
            rA.y = (c2[j][1] - mnA) * iA * g.y + b.y;
            rB.x = (c2[j][2] - mnB) * iB * g.x + b.x;
            rB.y = (c2[j][3] - mnB) * iB * g.y + b.y;
            *(float2*)(oA + n0) = rA;
            *(float2*)(oB + n0) = rB;
        }
    }
}

// ===================== launch (single kernel per call) =====================
extern "C" void kernel_launch(void* const* d_in, const int* in_sizes, int n_in,
                              void* d_out, int out_size) {
    const float* x     = (const float*)d_in[0];
    const float* graph = (const float*)d_in[1];
    const float* W_msg = (const float*)d_in[2];
    const float* b_msg = (const float*)d_in[3];
    const float* W_upd = (const float*)d_in[4];
    const float* b_upd = (const float*)d_in[5];
    const float* W_out = (const float*)d_in[6];
    const float* b_out = (const float*)d_in[7];
    const float* gamma = (const float*)d_in[8];
    const float* beta  = (const float*)d_in[9];
    float* out = (float*)d_out;

    cudaFuncSetAttribute(lgn_main, cudaFuncAttributeMaxDynamicSharedMemorySize, SMEM_BYTES);

    lgn_main<<<GRID_MAIN, NTHREADS, SMEM_BYTES>>>(
        x, graph, W_msg, b_msg, W_upd, b_upd, W_out, b_out, gamma, beta, out);
}